// round 2
// baseline (speedup 1.0000x reference)
#include <cuda_runtime.h>

// Interpolate1D: stride-2 linear upsample along dim 1.
// in:  [B=16, N=8192, C=256] fp32
// out: [B, 2N, C] fp32
//   out[b, 2k,   c] = x[b, k, c]
//   out[b, 2k+1, c] = 0.5*(x[b,k,c] + x[b,k+1,c])  (k < N-1)
//   out[b, 2N-1, c] = x[b, N-1, c]

namespace {
constexpr int B = 16;
constexpr int N = 8192;
constexpr int C = 256;
constexpr int C4 = C / 4;                     // 64 float4 per row
constexpr int HALF = C4 / 2;                  // 32: each thread does c and c+32
constexpr long TOTALT = (long)B * N * HALF;   // 4,194,304 threads
}

__global__ void interp1d_kernel(const float4* __restrict__ x,
                                float4* __restrict__ y) {
    long i = (long)blockIdx.x * blockDim.x + threadIdx.x;
    if (i >= TOTALT) return;

    int c   = (int)(i & (HALF - 1));   // 0..31
    long bn = i >> 5;                  // flattened (b*N + k)
    int k   = (int)(bn & (N - 1));

    long base = bn * C4 + c;
    // 4 independent loads issued up front (MLP=4 per thread)
    float4 cur0 = x[base];
    float4 cur1 = x[base + HALF];
    long nbase = (k < N - 1) ? base + C4 : base;
    float4 nxt0 = x[nbase];
    float4 nxt1 = x[nbase + HALF];

    float4 mid0, mid1;
    mid0.x = 0.5f * (cur0.x + nxt0.x);
    mid0.y = 0.5f * (cur0.y + nxt0.y);
    mid0.z = 0.5f * (cur0.z + nxt0.z);
    mid0.w = 0.5f * (cur0.w + nxt0.w);
    mid1.x = 0.5f * (cur1.x + nxt1.x);
    mid1.y = 0.5f * (cur1.y + nxt1.y);
    mid1.z = 0.5f * (cur1.z + nxt1.z);
    mid1.w = 0.5f * (cur1.w + nxt1.w);

    // even output row at 2*bn, odd (midpoint) row at 2*bn+1
    long o = (bn << 1) * C4 + c;
    __stcs(&y[o],             cur0);   // streaming: output never re-read
    __stcs(&y[o + HALF],      cur1);
    __stcs(&y[o + C4],        mid0);
    __stcs(&y[o + C4 + HALF], mid1);
}

extern "C" void kernel_launch(void* const* d_in, const int* in_sizes, int n_in,
                              void* d_out, int out_size) {
    const float4* x = (const float4*)d_in[0];
    float4* y = (float4*)d_out;

    const int threads = 256;
    const long blocks = (TOTALT + threads - 1) / threads;
    interp1d_kernel<<<(unsigned)blocks, threads>>>(x, y);
}

// round 3
// speedup vs baseline: 1.0005x; 1.0005x over previous
#include <cuda_runtime.h>
#include <cstdint>

// Interpolate1D: stride-2 linear upsample along dim 1.
// in:  [B=16, N=8192, C=256] fp32
// out: [B, 2N, C] fp32
//   out[b, 2k,   c] = x[b, k, c]
//   out[b, 2k+1, c] = 0.5*(x[b,k,c] + x[b,k+1,c])  (k < N-1)
//   out[b, 2N-1, c] = x[b, N-1, c]
//
// sm_103a: 256-bit global loads/stores (ld/st.global.v8.f32).
// Each thread handles one 32-byte chunk (8 floats) of one input row:
// reads cur(32B) + nxt(32B), writes even(32B) + odd(32B).

namespace {
constexpr int  B = 16;
constexpr int  N = 8192;
constexpr int  C = 256;            // floats per row
constexpr int  C8 = C / 8;         // 32 eight-float chunks per row
constexpr long TOTALT = (long)B * N * C8;  // 4,194,304 threads
}

__device__ __forceinline__ void ldg256(const float* p, float* v) {
    asm volatile("ld.global.nc.v8.f32 {%0,%1,%2,%3,%4,%5,%6,%7}, [%8];"
                 : "=f"(v[0]), "=f"(v[1]), "=f"(v[2]), "=f"(v[3]),
                   "=f"(v[4]), "=f"(v[5]), "=f"(v[6]), "=f"(v[7])
                 : "l"(p));
}

__device__ __forceinline__ void stg256_cs(float* p, const float* v) {
    asm volatile("st.global.cs.v8.f32 [%0], {%1,%2,%3,%4,%5,%6,%7,%8};"
                 :: "l"(p),
                    "f"(v[0]), "f"(v[1]), "f"(v[2]), "f"(v[3]),
                    "f"(v[4]), "f"(v[5]), "f"(v[6]), "f"(v[7])
                 : "memory");
}

__global__ void interp1d_kernel(const float* __restrict__ x,
                                float* __restrict__ y) {
    long i = (long)blockIdx.x * blockDim.x + threadIdx.x;
    if (i >= TOTALT) return;

    int  c  = (int)(i & (C8 - 1));   // chunk 0..31 within row
    long bn = i >> 5;                // flattened (b*N + k)
    int  k  = (int)(bn & (N - 1));

    const float* pc = x + bn * C + c * 8;
    const float* pn = (k < N - 1) ? pc + C : pc;

    float cur[8], nxt[8];
    ldg256(pc, cur);
    ldg256(pn, nxt);

    float mid[8];
#pragma unroll
    for (int j = 0; j < 8; j++) mid[j] = 0.5f * (cur[j] + nxt[j]);

    // even output row at 2*bn, odd (midpoint) row at 2*bn+1
    float* po = y + (bn << 1) * C + c * 8;
    stg256_cs(po,     cur);
    stg256_cs(po + C, mid);
}

extern "C" void kernel_launch(void* const* d_in, const int* in_sizes, int n_in,
                              void* d_out, int out_size) {
    const float* x = (const float*)d_in[0];
    float* y = (float*)d_out;

    const int threads = 256;
    const long blocks = (TOTALT + threads - 1) / threads;
    interp1d_kernel<<<(unsigned)blocks, threads>>>(x, y);
}